// round 16
// baseline (speedup 1.0000x reference)
#include <cuda_runtime.h>
#include <cuda_fp16.h>
#include <cstdint>

#define N_NODES 50000
#define N_PAD   50176           // 196 * 256
#define D 256
#define E_MAX 800000

// ---------------- scratch (static device globals; no allocation) ----------------
__device__ int   g_deg[N_NODES];
__device__ int   g_rowptr[N_NODES + 1];
__device__ int   g_cursor[N_NODES];
__device__ int   g_eidx[E_MAX];
// current-layer features fp16 pairs: [row][t(128)] u32
__device__ __align__(16) uint32_t g_feat[(size_t)N_NODES * 128];
// A k-tiled swizzled: [kt(16)][row(N_PAD)][16 u32]; seg s of row r at phys (s+(r>>1))&3
__device__ __align__(16) uint32_t g_A[(size_t)16 * N_PAD * 16];
// B^T k-tiled swizzled: [layer][kt(16)][n(256)][16 u32]
__device__ __align__(16) uint32_t g_Bt[2 * 16 * 256 * 16];

// ---------------- small helpers ----------------
__device__ __forceinline__ uint32_t smem_to_u32(const void* p) {
    uint32_t a;
    asm("{ .reg .u64 t; cvta.to.shared.u64 t, %1; cvt.u32.u64 %0, t; }" : "=r"(a) : "l"(p));
    return a;
}

__device__ __forceinline__ uint32_t pack_h2(__half a, __half b) {
    __half2 h = __halves2half2(a, b);
    return *reinterpret_cast<uint32_t*>(&h);
}

__device__ __forceinline__ uint32_t pack_f2h2(float a, float b) {
    return pack_h2(__float2half_rn(a), __float2half_rn(b));
}

__device__ __forceinline__ uint32_t hadd2(uint32_t a, uint32_t b) {
    uint32_t r;
    asm("add.rn.f16x2 %0, %1, %2;" : "=r"(r) : "r"(a), "r"(b));
    return r;
}

__device__ __forceinline__ void acc_u4(float* a, uint4 u) {
    float2 f0 = __half22float2(*reinterpret_cast<__half2*>(&u.x));
    float2 f1 = __half22float2(*reinterpret_cast<__half2*>(&u.y));
    float2 f2 = __half22float2(*reinterpret_cast<__half2*>(&u.z));
    float2 f3 = __half22float2(*reinterpret_cast<__half2*>(&u.w));
    a[0] += f0.x; a[1] += f0.y; a[2] += f1.x; a[3] += f1.y;
    a[4] += f2.x; a[5] += f2.y; a[6] += f3.x; a[7] += f3.y;
}

#define LDSM_X4(r0, r1, r2, r3, addr) \
    asm volatile("ldmatrix.sync.aligned.m8n8.x4.shared.b16 {%0,%1,%2,%3}, [%4];" \
        : "=r"(r0), "=r"(r1), "=r"(r2), "=r"(r3) : "r"(addr))
#define LDSM_X2(r0, r1, addr) \
    asm volatile("ldmatrix.sync.aligned.m8n8.x2.shared.b16 {%0,%1}, [%2];" \
        : "=r"(r0), "=r"(r1) : "r"(addr))

__device__ __forceinline__ void mma_f32acc(float* c, const uint32_t* a, uint32_t b0, uint32_t b1) {
    asm volatile(
        "mma.sync.aligned.m16n8k16.row.col.f32.f16.f16.f32 "
        "{%0,%1,%2,%3}, {%4,%5,%6,%7}, {%8,%9}, {%0,%1,%2,%3};\n"
        : "+f"(c[0]), "+f"(c[1]), "+f"(c[2]), "+f"(c[3])
        : "r"(a[0]), "r"(a[1]), "r"(a[2]), "r"(a[3]), "r"(b0), "r"(b1));
}

#define BULK_CP(dst, src, size, mbar) \
    asm volatile("cp.async.bulk.shared::cluster.global.mbarrier::complete_tx::bytes [%0], [%1], %2, [%3];" \
        :: "r"(dst), "l"(src), "r"(size), "r"(mbar) : "memory")

#define MBARRIER_INIT(mbar, count) \
    asm volatile("mbarrier.init.shared.b64 [%0], %1;" \
        :: "r"((uint32_t)(mbar)), "r"((uint32_t)(count)) : "memory")
#define MBARRIER_EXPECT_TX(mbar, tx) \
    asm volatile("mbarrier.arrive.expect_tx.shared.b64 _, [%0], %1;" \
        :: "r"((uint32_t)(mbar)), "r"((uint32_t)(tx)) : "memory")

#define MBARRIER_WAIT_PARITY(mbar, parity) do { \
    uint32_t _mbar = (uint32_t)(mbar); \
    uint32_t _parity = (uint32_t)(parity); \
    uint32_t _done; \
    asm volatile("{\n\t.reg .pred p;\n\t" \
        "mbarrier.try_wait.parity.acquire.cta.shared::cta.b64 p, [%1], %2;\n\t" \
        "selp.b32 %0, 1, 0, p;\n\t}" : "=r"(_done) : "r"(_mbar), "r"(_parity) : "memory"); \
    if (!_done) { \
        asm volatile("{\n\t.reg .pred P1;\n\t" \
            "WAIT_LOOP_%=:\n\t" \
            "mbarrier.try_wait.parity.acquire.cta.shared::cta.b64 P1, [%0], %1, 0x989680;\n\t" \
            "@P1 bra.uni WAIT_DONE_%=;\n\t" \
            "bra.uni WAIT_LOOP_%=;\n\t" \
            "WAIT_DONE_%=:\n\t}" :: "r"(_mbar), "r"(_parity) : "memory"); \
    } \
} while(0)

// ------ prep: degree count + x->fp16 + W->B^T (3-way disjoint blocks) ------
__global__ void prep_kernel(const int* __restrict__ ei, const float* __restrict__ x,
                            const float* __restrict__ W1l, const float* __restrict__ W1r,
                            const float* __restrict__ W2l, const float* __restrict__ W2r,
                            int E, int nb_count, int nb_conv) {
    int b = blockIdx.x;
    if (b < nb_count) {
        int e = b * 256 + threadIdx.x;
        if (e < E) atomicAdd(&g_deg[ei[E + e]], 1);
    } else if (b < nb_count + nb_conv) {
        int idx = (b - nb_count) * 256 + threadIdx.x;
        if (idx < N_NODES * 128) {
            float2 v = *(const float2*)&x[(size_t)idx * 2];
            g_feat[idx] = pack_f2h2(v.x, v.y);
        }
    } else {
        int idx = (b - nb_count - nb_conv) * 256 + threadIdx.x;  // 0..131071
        int layer = idx >> 16;
        int n  = (idx >> 8) & 255;
        int k2 = idx & 255;
        int k  = k2 * 2;
        const float* Wl = layer ? W2l : W1l;
        const float* Wr = layer ? W2r : W1r;
        float v0, v1;
        if (k < 256) { v0 = Wl[k * 256 + n]; v1 = Wl[(k + 1) * 256 + n]; }
        else         { v0 = Wr[(k - 256) * 256 + n]; v1 = Wr[(k - 255) * 256 + n]; }
        int kt   = k2 >> 4;
        int seg  = (k2 >> 2) & 3;
        int phys = (seg + (n >> 1)) & 3;
        int inner = k2 & 3;
        g_Bt[(((size_t)layer * 16 + kt) * 256 + n) * 16 + phys * 4 + inner] = pack_f2h2(v0, v1);
    }
}

// single-block full scan
#define SCAN_PER_T 49
__global__ void scanall_kernel(int E) {
    __shared__ int ssum[1024];
    int t = threadIdx.x;
    int base = t * SCAN_PER_T;
    int s = 0;
#pragma unroll 7
    for (int i = 0; i < SCAN_PER_T; i++) {
        int idx = base + i;
        int v = (idx < N_NODES) ? g_deg[idx] : 0;
        if (idx < N_NODES) g_rowptr[idx] = s;
        s += v;
    }
    ssum[t] = s;
    __syncthreads();
    for (int off = 1; off < 1024; off <<= 1) {
        int v = (t >= off) ? ssum[t - off] : 0;
        __syncthreads();
        ssum[t] += v;
        __syncthreads();
    }
    int tbase = ssum[t] - s;
#pragma unroll 7
    for (int i = 0; i < SCAN_PER_T; i++) {
        int idx = base + i;
        if (idx < N_NODES) {
            int r = g_rowptr[idx] + tbase;
            g_rowptr[idx] = r;
            g_cursor[idx] = r;
            g_deg[idx]    = 0;
        }
    }
    if (t == 0) g_rowptr[N_NODES] = E;
}

__global__ void scatter_kernel(const int* __restrict__ ei, int E) {
    int e = blockIdx.x * blockDim.x + threadIdx.x;
    if (e < E) {
        int src = ei[e];
        int dst = ei[E + e];
        int pos = atomicAdd(&g_cursor[dst], 1);
        g_eidx[pos] = src;
    }
}

// ---------------- mean aggregation: warp/row, pairwise fp16 pre-add ----------------
__global__ void aggregate_kernel() {
    int w    = threadIdx.x >> 5;
    int lane = threadIdx.x & 31;
    int row  = blockIdx.x * 4 + w;
    const uint4* __restrict__ feat4 = (const uint4*)g_feat;

    int start = g_rowptr[row];
    int end   = g_rowptr[row + 1];

    float acc[8];
#pragma unroll
    for (int i = 0; i < 8; i++) acc[i] = 0.f;

    int e = start;
    for (; e + 4 <= end; e += 4) {
        int s0 = g_eidx[e],     s1 = g_eidx[e + 1];
        int s2 = g_eidx[e + 2], s3 = g_eidx[e + 3];
        uint4 u0 = feat4[s0 * 32 + lane];
        uint4 u1 = feat4[s1 * 32 + lane];
        uint4 u2 = feat4[s2 * 32 + lane];
        uint4 u3 = feat4[s3 * 32 + lane];
        uint4 p01, p23;
        p01.x = hadd2(u0.x, u1.x); p01.y = hadd2(u0.y, u1.y);
        p01.z = hadd2(u0.z, u1.z); p01.w = hadd2(u0.w, u1.w);
        p23.x = hadd2(u2.x, u3.x); p23.y = hadd2(u2.y, u3.y);
        p23.z = hadd2(u2.z, u3.z); p23.w = hadd2(u2.w, u3.w);
        acc_u4(acc, p01);
        acc_u4(acc, p23);
    }
    if (e + 2 <= end) {
        uint4 u0 = feat4[g_eidx[e] * 32 + lane];
        uint4 u1 = feat4[g_eidx[e + 1] * 32 + lane];
        uint4 p;
        p.x = hadd2(u0.x, u1.x); p.y = hadd2(u0.y, u1.y);
        p.z = hadd2(u0.z, u1.z); p.w = hadd2(u0.w, u1.w);
        acc_u4(acc, p);
        e += 2;
    }
    if (e < end) {
        uint4 u = feat4[g_eidx[e] * 32 + lane];
        acc_u4(acc, u);
    }

    int deg = end - start;
    float scale = (deg > 0) ? 1.f / (float)deg : 0.f;
    uint4 o;
    o.x = pack_f2h2(acc[0] * scale, acc[1] * scale);
    o.y = pack_f2h2(acc[2] * scale, acc[3] * scale);
    o.z = pack_f2h2(acc[4] * scale, acc[5] * scale);
    o.w = pack_f2h2(acc[6] * scale, acc[7] * scale);
    int kt   = lane >> 2;
    int phys = ((lane & 3) + (row >> 1)) & 3;
    uint4* A4 = (uint4*)g_A;
    A4[((size_t)kt * N_PAD + row) * 4 + phys]       = o;
    A4[((size_t)(kt + 8) * N_PAD + row) * 4 + phys] = feat4[row * 32 + lane];
}

// ---------------- fp16 mma.sync GEMM: 3-stage bulk pipeline + staged epilogue ----
#define A_TILE_B 16384
#define B_TILE_B 8192
#define STAGE_B  (A_TILE_B + B_TILE_B)   // 24576
#define N_STAGE  3
#define SM_DYN   (N_STAGE * STAGE_B)     // 73728
#define EP16_STRIDE 272                  // bytes/row: 128 fp16 + pad (256 rows = 69632 <= SM_DYN)
#define EPF_STRIDE  528                  // bytes/row: 128 f32 + pad (128 rows = 67584 <= SM_DYN)

template <bool RELU, bool OUT_FP16>
__global__ __launch_bounds__(512, 1) void gemm_f16_kernel(
    int layer, const float* __restrict__ bias, float* __restrict__ out_param)
{
    extern __shared__ char dsm[];
    __shared__ float bias_s[128];
    __shared__ __align__(8) unsigned long long mbar_s[N_STAGE];

    int tid  = threadIdx.x;
    int wid  = tid >> 5;
    int lid  = tid & 31;
    int g    = lid >> 2;
    int tg   = lid & 3;
    int row0 = blockIdx.x * 256;
    int n0   = blockIdx.y * 128;

    int warp_m = (wid & 3) * 64;
    int warp_n = (wid >> 2) * 32;

    if (tid < 128) bias_s[tid] = bias[n0 + tid];

    uint32_t s_base    = smem_to_u32(dsm);
    uint32_t mbar_base = smem_to_u32(mbar_s);

    if (tid == 0) {
#pragma unroll
        for (int s = 0; s < N_STAGE; s++) MBARRIER_INIT(mbar_base + s * 8, 1);
    }
    __syncthreads();

    int lrA = (lid & 7) + ((lid >> 3) & 1) * 8;
    uint32_t a_off0 = (uint32_t)(lrA * 64 + ((((lid >> 4))     + (lrA >> 1)) & 3) * 16);
    uint32_t a_off1 = (uint32_t)(lrA * 64 + ((((lid >> 4)) + 2 + (lrA >> 1)) & 3) * 16);
    int lrB = lid & 7;
    uint32_t b_off0 = (uint32_t)(lrB * 64 + (((((lid & 15) >> 3))     + (lrB >> 1)) & 3) * 16);
    uint32_t b_off1 = (uint32_t)(lrB * 64 + (((((lid & 15) >> 3)) + 2 + (lrB >> 1)) & 3) * 16);

    float acc[4][4][4];
#pragma unroll
    for (int mi = 0; mi < 4; mi++)
#pragma unroll
        for (int ni = 0; ni < 4; ni++)
#pragma unroll
            for (int r = 0; r < 4; r++) acc[mi][ni][r] = 0.f;

    const char* aBase = (const char*)g_A + (size_t)row0 * 64;
    const char* bBase = (const char*)g_Bt + ((size_t)layer * 16 * 256 + n0) * 64;

    auto issue = [&](int kt, int st) {
        uint32_t mb = mbar_base + st * 8;
        MBARRIER_EXPECT_TX(mb, STAGE_B);
        uint32_t d = s_base + st * STAGE_B;
        BULK_CP(d,            aBase + (size_t)kt * N_PAD * 64, A_TILE_B, mb);
        BULK_CP(d + A_TILE_B, bBase + (size_t)kt * 256 * 64,   B_TILE_B, mb);
    };

    if (tid == 0) { issue(0, 0); issue(1, 1); }

    for (int kt = 0; kt < 16; kt++) {
        int st = kt % N_STAGE;
        if (tid == 0 && kt + 2 < 16) issue(kt + 2, (kt + 2) % N_STAGE);

        MBARRIER_WAIT_PARITY(mbar_base + st * 8, (kt / N_STAGE) & 1);

        uint32_t sa = s_base + st * STAGE_B;
        uint32_t sb = sa + A_TILE_B;

#pragma unroll
        for (int ks = 0; ks < 2; ks++) {
            uint32_t ao = ks ? a_off1 : a_off0;
            uint32_t bo = ks ? b_off1 : b_off0;
            uint32_t bh[4][2];
#pragma unroll
            for (int ni = 0; ni < 4; ni++)
                LDSM_X2(bh[ni][0], bh[ni][1], sb + (uint32_t)((warp_n + ni * 8) * 64) + bo);
#pragma unroll
            for (int mi = 0; mi < 4; mi++) {
                uint32_t ah[4];
                LDSM_X4(ah[0], ah[1], ah[2], ah[3], sa + (uint32_t)((warp_m + mi * 16) * 64) + ao);
#pragma unroll
                for (int ni = 0; ni < 4; ni++) mma_f32acc(acc[mi][ni], ah, bh[ni][0], bh[ni][1]);
            }
        }
        __syncthreads();
    }

    // ---- staged, coalesced epilogue ----
    if (OUT_FP16) {
        // stage fp16 results into smem [256 rows][EP16_STRIDE]
#pragma unroll
        for (int mi = 0; mi < 4; mi++) {
#pragma unroll
            for (int ni = 0; ni < 4; ni++) {
                int lr = warp_m + mi * 16 + g;
                int c  = warp_n + ni * 8 + tg * 2;
                float bx = bias_s[c], by = bias_s[c + 1];
                float2 v0, v1;
                v0.x = acc[mi][ni][0] + bx; v0.y = acc[mi][ni][1] + by;
                v1.x = acc[mi][ni][2] + bx; v1.y = acc[mi][ni][3] + by;
                if (RELU) {
                    v0.x = fmaxf(v0.x, 0.f); v0.y = fmaxf(v0.y, 0.f);
                    v1.x = fmaxf(v1.x, 0.f); v1.y = fmaxf(v1.y, 0.f);
                }
                *(uint32_t*)(dsm + lr * EP16_STRIDE + c * 2)       = pack_f2h2(v0.x, v0.y);
                *(uint32_t*)(dsm + (lr + 8) * EP16_STRIDE + c * 2) = pack_f2h2(v1.x, v1.y);
            }
        }
        __syncthreads();
        // cooperative coalesced store: 256 rows x 256B (half feature row)
#pragma unroll
        for (int i = 0; i < 8; i++) {
            int idx = i * 512 + tid;
            int r   = idx >> 4;
            int seg = idx & 15;
            int gr  = row0 + r;
            if (gr < N_NODES) {
                uint4 v = *(uint4*)(dsm + r * EP16_STRIDE + seg * 16);
                *(uint4*)((char*)g_feat + (size_t)gr * 512 + n0 * 2 + seg * 16) = v;
            }
        }
    } else {
        // f32 output in two 128-row halves
#pragma unroll
        for (int h = 0; h < 2; h++) {
            if (h) __syncthreads();   // protect smem reuse between halves
#pragma unroll
            for (int mh = 0; mh < 2; mh++) {
                int mi = 2 * h + mh;
#pragma unroll
                for (int ni = 0; ni < 4; ni++) {
                    int lr = (warp_m >> 1) + mh * 16 + g;
                    int c  = warp_n + ni * 8 + tg * 2;
                    float bx = bias_s[c], by = bias_s[c + 1];
                    float2 v0, v1;
                    v0.x = acc[mi][ni][0] + bx; v0.y = acc[mi][ni][1] + by;
                    v1.x = acc[mi][ni][2] + bx; v1.y = acc[mi][ni][3] + by;
                    *(float2*)(dsm + lr * EPF_STRIDE + c * 4)       = v0;
                    *(float2*)(dsm + (lr + 8) * EPF_STRIDE + c * 4) = v1;
                }
            }
            __syncthreads();
            // cooperative store: 128 rows x 512B (half output row)
#pragma unroll
            for (int i = 0; i < 8; i++) {
                int idx = i * 512 + tid;
                int r   = idx >> 5;
                int seg = idx & 31;
                int gr  = row0 + h * 32 + r + (r & ~31);
                if (gr < N_NODES) {
                    uint4 v = *(uint4*)(dsm + r * EPF_STRIDE + seg * 16);
                    *(uint4*)((char*)out_param + (size_t)gr * 1024 + n0 * 4 + seg * 16) = v;
                }
            }
        }
    }
}

// ---------------- launch ----------------
extern "C" void kernel_launch(void* const* d_in, const int* in_sizes, int n_in,
                              void* d_out, int out_size)
{
    const float* x   = (const float*)d_in[0];
    const int*   ei  = (const int*)d_in[1];     // JAX randint -> int32 (x64 disabled)
    const float* W1l = (const float*)d_in[2];
    const float* b1  = (const float*)d_in[3];
    const float* W1r = (const float*)d_in[4];
    const float* W2l = (const float*)d_in[5];
    const float* b2  = (const float*)d_in[6];
    const float* W2r = (const float*)d_in[7];
    float*       out = (float*)d_out;

    int E = in_sizes[1] / 2;
    if (E > E_MAX) E = E_MAX;

    cudaFuncSetAttribute(gemm_f16_kernel<true, true>,
                         cudaFuncAttributeMaxDynamicSharedMemorySize, SM_DYN);
    cudaFuncSetAttribute(gemm_f16_kernel<false, false>,
                         cudaFuncAttributeMaxDynamicSharedMemorySize, SM_DYN);

    int nb_count = (E + 255) / 256;
    int nb_conv  = (N_NODES * 128 + 255) / 256;
    int nb_w     = 512;

    // 0: degree count + x->fp16 + W convert (fused)
    prep_kernel<<<nb_count + nb_conv + nb_w, 256>>>(ei, x, W1l, W1r, W2l, W2r,
                                                    E, nb_count, nb_conv);
    // 1: scan (re-zeros deg for next replay)
    scanall_kernel<<<1, 1024>>>(E);
    // 2: CSR scatter
    scatter_kernel<<<nb_count, 256>>>(ei, E);
    // 3: layer-1 aggregation (profiled slot)
    aggregate_kernel<<<N_NODES / 4, 128>>>();

    dim3 ggrid((N_PAD + 255) / 256, 2);   // 196 x 2
    // 4: layer-1 GEMM -> g_feat (fp16 relu h)
    gemm_f16_kernel<true, true><<<ggrid, 512, SM_DYN>>>(0, b1, nullptr);
    // 5: layer-2 aggregation
    aggregate_kernel<<<N_NODES / 4, 128>>>();
    // 6: layer-2 GEMM -> out (f32)
    gemm_f16_kernel<false, false><<<ggrid, 512, SM_DYN>>>(1, b2, out);
}

// round 17
// speedup vs baseline: 1.0485x; 1.0485x over previous
#include <cuda_runtime.h>
#include <cuda_fp16.h>
#include <cstdint>

#define N_NODES 50000
#define N_PAD   50176           // 196 * 256 (also 392 * 128)
#define D 256
#define E_MAX 800000

// ---------------- scratch (static device globals; no allocation) ----------------
__device__ int   g_deg[N_NODES];
__device__ int   g_rowptr[N_NODES + 1];
__device__ int   g_cursor[N_NODES];
__device__ int   g_eidx[E_MAX];
// current-layer features fp16 pairs: [row][t(128)] u32
__device__ __align__(16) uint32_t g_feat[(size_t)N_NODES * 128];
// A k-tiled swizzled: [kt(16)][row(N_PAD)][16 u32]; seg s of row r at phys (s+(r>>1))&3
__device__ __align__(16) uint32_t g_A[(size_t)16 * N_PAD * 16];
// B^T k-tiled swizzled: [layer][kt(16)][n(256)][16 u32]
__device__ __align__(16) uint32_t g_Bt[2 * 16 * 256 * 16];

// ---------------- small helpers ----------------
__device__ __forceinline__ uint32_t smem_to_u32(const void* p) {
    uint32_t a;
    asm("{ .reg .u64 t; cvta.to.shared.u64 t, %1; cvt.u32.u64 %0, t; }" : "=r"(a) : "l"(p));
    return a;
}

__device__ __forceinline__ uint32_t pack_h2(__half a, __half b) {
    __half2 h = __halves2half2(a, b);
    return *reinterpret_cast<uint32_t*>(&h);
}

__device__ __forceinline__ uint32_t pack_f2h2(float a, float b) {
    return pack_h2(__float2half_rn(a), __float2half_rn(b));
}

__device__ __forceinline__ uint32_t hadd2(uint32_t a, uint32_t b) {
    uint32_t r;
    asm("add.rn.f16x2 %0, %1, %2;" : "=r"(r) : "r"(a), "r"(b));
    return r;
}

__device__ __forceinline__ void acc_u4(float* a, uint4 u) {
    float2 f0 = __half22float2(*reinterpret_cast<__half2*>(&u.x));
    float2 f1 = __half22float2(*reinterpret_cast<__half2*>(&u.y));
    float2 f2 = __half22float2(*reinterpret_cast<__half2*>(&u.z));
    float2 f3 = __half22float2(*reinterpret_cast<__half2*>(&u.w));
    a[0] += f0.x; a[1] += f0.y; a[2] += f1.x; a[3] += f1.y;
    a[4] += f2.x; a[5] += f2.y; a[6] += f3.x; a[7] += f3.y;
}

#define LDSM_X4(r0, r1, r2, r3, addr) \
    asm volatile("ldmatrix.sync.aligned.m8n8.x4.shared.b16 {%0,%1,%2,%3}, [%4];" \
        : "=r"(r0), "=r"(r1), "=r"(r2), "=r"(r3) : "r"(addr))
#define LDSM_X2(r0, r1, addr) \
    asm volatile("ldmatrix.sync.aligned.m8n8.x2.shared.b16 {%0,%1}, [%2];" \
        : "=r"(r0), "=r"(r1) : "r"(addr))

__device__ __forceinline__ void mma_f32acc(float* c, const uint32_t* a, uint32_t b0, uint32_t b1) {
    asm volatile(
        "mma.sync.aligned.m16n8k16.row.col.f32.f16.f16.f32 "
        "{%0,%1,%2,%3}, {%4,%5,%6,%7}, {%8,%9}, {%0,%1,%2,%3};\n"
        : "+f"(c[0]), "+f"(c[1]), "+f"(c[2]), "+f"(c[3])
        : "r"(a[0]), "r"(a[1]), "r"(a[2]), "r"(a[3]), "r"(b0), "r"(b1));
}

#define BULK_CP(dst, src, size, mbar) \
    asm volatile("cp.async.bulk.shared::cluster.global.mbarrier::complete_tx::bytes [%0], [%1], %2, [%3];" \
        :: "r"(dst), "l"(src), "r"(size), "r"(mbar) : "memory")

#define MBARRIER_INIT(mbar, count) \
    asm volatile("mbarrier.init.shared.b64 [%0], %1;" \
        :: "r"((uint32_t)(mbar)), "r"((uint32_t)(count)) : "memory")
#define MBARRIER_EXPECT_TX(mbar, tx) \
    asm volatile("mbarrier.arrive.expect_tx.shared.b64 _, [%0], %1;" \
        :: "r"((uint32_t)(mbar)), "r"((uint32_t)(tx)) : "memory")

#define MBARRIER_WAIT_PARITY(mbar, parity) do { \
    uint32_t _mbar = (uint32_t)(mbar); \
    uint32_t _parity = (uint32_t)(parity); \
    uint32_t _done; \
    asm volatile("{\n\t.reg .pred p;\n\t" \
        "mbarrier.try_wait.parity.acquire.cta.shared::cta.b64 p, [%1], %2;\n\t" \
        "selp.b32 %0, 1, 0, p;\n\t}" : "=r"(_done) : "r"(_mbar), "r"(_parity) : "memory"); \
    if (!_done) { \
        asm volatile("{\n\t.reg .pred P1;\n\t" \
            "WAIT_LOOP_%=:\n\t" \
            "mbarrier.try_wait.parity.acquire.cta.shared::cta.b64 P1, [%0], %1, 0x989680;\n\t" \
            "@P1 bra.uni WAIT_DONE_%=;\n\t" \
            "bra.uni WAIT_LOOP_%=;\n\t" \
            "WAIT_DONE_%=:\n\t}" :: "r"(_mbar), "r"(_parity) : "memory"); \
    } \
} while(0)

// ------ prep: degree count + x->fp16 + W->B^T (3-way disjoint blocks) ------
__global__ void prep_kernel(const int* __restrict__ ei, const float* __restrict__ x,
                            const float* __restrict__ W1l, const float* __restrict__ W1r,
                            const float* __restrict__ W2l, const float* __restrict__ W2r,
                            int E, int nb_count, int nb_conv) {
    int b = blockIdx.x;
    if (b < nb_count) {
        int e = b * 256 + threadIdx.x;
        if (e < E) atomicAdd(&g_deg[ei[E + e]], 1);
    } else if (b < nb_count + nb_conv) {
        int idx = (b - nb_count) * 256 + threadIdx.x;
        if (idx < N_NODES * 128) {
            float2 v = *(const float2*)&x[(size_t)idx * 2];
            g_feat[idx] = pack_f2h2(v.x, v.y);
        }
    } else {
        int idx = (b - nb_count - nb_conv) * 256 + threadIdx.x;  // 0..131071
        int layer = idx >> 16;
        int n  = (idx >> 8) & 255;
        int k2 = idx & 255;
        int k  = k2 * 2;
        const float* Wl = layer ? W2l : W1l;
        const float* Wr = layer ? W2r : W1r;
        float v0, v1;
        if (k < 256) { v0 = Wl[k * 256 + n]; v1 = Wl[(k + 1) * 256 + n]; }
        else         { v0 = Wr[(k - 256) * 256 + n]; v1 = Wr[(k - 255) * 256 + n]; }
        int kt   = k2 >> 4;
        int seg  = (k2 >> 2) & 3;
        int phys = (seg + (n >> 1)) & 3;
        int inner = k2 & 3;
        g_Bt[(((size_t)layer * 16 + kt) * 256 + n) * 16 + phys * 4 + inner] = pack_f2h2(v0, v1);
    }
}

// single-block full scan
#define SCAN_PER_T 49
__global__ void scanall_kernel(int E) {
    __shared__ int ssum[1024];
    int t = threadIdx.x;
    int base = t * SCAN_PER_T;
    int s = 0;
#pragma unroll 7
    for (int i = 0; i < SCAN_PER_T; i++) {
        int idx = base + i;
        int v = (idx < N_NODES) ? g_deg[idx] : 0;
        if (idx < N_NODES) g_rowptr[idx] = s;
        s += v;
    }
    ssum[t] = s;
    __syncthreads();
    for (int off = 1; off < 1024; off <<= 1) {
        int v = (t >= off) ? ssum[t - off] : 0;
        __syncthreads();
        ssum[t] += v;
        __syncthreads();
    }
    int tbase = ssum[t] - s;
#pragma unroll 7
    for (int i = 0; i < SCAN_PER_T; i++) {
        int idx = base + i;
        if (idx < N_NODES) {
            int r = g_rowptr[idx] + tbase;
            g_rowptr[idx] = r;
            g_cursor[idx] = r;
            g_deg[idx]    = 0;
        }
    }
    if (t == 0) g_rowptr[N_NODES] = E;
}

__global__ void scatter_kernel(const int* __restrict__ ei, int E) {
    int e = blockIdx.x * blockDim.x + threadIdx.x;
    if (e < E) {
        int src = ei[e];
        int dst = ei[E + e];
        int pos = atomicAdd(&g_cursor[dst], 1);
        g_eidx[pos] = src;
    }
}

// ---------------- mean aggregation: warp/row, pairwise fp16 pre-add ----------------
__global__ void aggregate_kernel() {
    int w    = threadIdx.x >> 5;
    int lane = threadIdx.x & 31;
    int row  = blockIdx.x * 4 + w;
    const uint4* __restrict__ feat4 = (const uint4*)g_feat;

    int start = g_rowptr[row];
    int end   = g_rowptr[row + 1];

    float acc[8];
#pragma unroll
    for (int i = 0; i < 8; i++) acc[i] = 0.f;

    int e = start;
    for (; e + 4 <= end; e += 4) {
        int s0 = g_eidx[e],     s1 = g_eidx[e + 1];
        int s2 = g_eidx[e + 2], s3 = g_eidx[e + 3];
        uint4 u0 = feat4[s0 * 32 + lane];
        uint4 u1 = feat4[s1 * 32 + lane];
        uint4 u2 = feat4[s2 * 32 + lane];
        uint4 u3 = feat4[s3 * 32 + lane];
        uint4 p01, p23;
        p01.x = hadd2(u0.x, u1.x); p01.y = hadd2(u0.y, u1.y);
        p01.z = hadd2(u0.z, u1.z); p01.w = hadd2(u0.w, u1.w);
        p23.x = hadd2(u2.x, u3.x); p23.y = hadd2(u2.y, u3.y);
        p23.z = hadd2(u2.z, u3.z); p23.w = hadd2(u2.w, u3.w);
        acc_u4(acc, p01);
        acc_u4(acc, p23);
    }
    if (e + 2 <= end) {
        uint4 u0 = feat4[g_eidx[e] * 32 + lane];
        uint4 u1 = feat4[g_eidx[e + 1] * 32 + lane];
        uint4 p;
        p.x = hadd2(u0.x, u1.x); p.y = hadd2(u0.y, u1.y);
        p.z = hadd2(u0.z, u1.z); p.w = hadd2(u0.w, u1.w);
        acc_u4(acc, p);
        e += 2;
    }
    if (e < end) {
        uint4 u = feat4[g_eidx[e] * 32 + lane];
        acc_u4(acc, u);
    }

    int deg = end - start;
    float scale = (deg > 0) ? 1.f / (float)deg : 0.f;
    uint4 o;
    o.x = pack_f2h2(acc[0] * scale, acc[1] * scale);
    o.y = pack_f2h2(acc[2] * scale, acc[3] * scale);
    o.z = pack_f2h2(acc[4] * scale, acc[5] * scale);
    o.w = pack_f2h2(acc[6] * scale, acc[7] * scale);
    int kt   = lane >> 2;
    int phys = ((lane & 3) + (row >> 1)) & 3;
    uint4* A4 = (uint4*)g_A;
    A4[((size_t)kt * N_PAD + row) * 4 + phys]       = o;
    A4[((size_t)(kt + 8) * N_PAD + row) * 4 + phys] = feat4[row * 32 + lane];
}

// ---------------- fp16 mma.sync GEMM: BM=128, BN=128, 256 thr, occupancy 2 ------
#define A_TILE_B 8192
#define B_TILE_B 8192
#define STAGE_B  (A_TILE_B + B_TILE_B)   // 16384
#define N_STAGE  3
#define SM_DYN   (N_STAGE * STAGE_B)     // 49152 -> 2 CTAs/SM

template <bool RELU, bool OUT_FP16>
__global__ __launch_bounds__(256, 2) void gemm_f16_kernel(
    int layer, const float* __restrict__ bias, float* __restrict__ out_param)
{
    extern __shared__ char dsm[];
    __shared__ float bias_s[128];
    __shared__ __align__(8) unsigned long long mbar_s[N_STAGE];

    int tid  = threadIdx.x;
    int wid  = tid >> 5;          // 0..7
    int lid  = tid & 31;
    int g    = lid >> 2;
    int tg   = lid & 3;
    int row0 = blockIdx.x * 128;
    int n0   = blockIdx.y * 128;

    int warp_m = (wid & 1) * 64;     // 2 warps in M
    int warp_n = (wid >> 1) * 32;    // 4 warps in N

    if (tid < 128) bias_s[tid] = bias[n0 + tid];

    uint32_t s_base    = smem_to_u32(dsm);
    uint32_t mbar_base = smem_to_u32(mbar_s);

    if (tid == 0) {
#pragma unroll
        for (int s = 0; s < N_STAGE; s++) MBARRIER_INIT(mbar_base + s * 8, 1);
    }
    __syncthreads();

    // per-lane ldmatrix offsets; row0/n0 are multiples of 128 so local-row swizzle == global
    int lrA = (lid & 7) + ((lid >> 3) & 1) * 8;
    uint32_t a_off0 = (uint32_t)(lrA * 64 + ((((lid >> 4))     + (lrA >> 1)) & 3) * 16);
    uint32_t a_off1 = (uint32_t)(lrA * 64 + ((((lid >> 4)) + 2 + (lrA >> 1)) & 3) * 16);
    int lrB = lid & 7;
    uint32_t b_off0 = (uint32_t)(lrB * 64 + (((((lid & 15) >> 3))     + (lrB >> 1)) & 3) * 16);
    uint32_t b_off1 = (uint32_t)(lrB * 64 + (((((lid & 15) >> 3)) + 2 + (lrB >> 1)) & 3) * 16);

    float acc[4][4][4];
#pragma unroll
    for (int mi = 0; mi < 4; mi++)
#pragma unroll
        for (int ni = 0; ni < 4; ni++)
#pragma unroll
            for (int r = 0; r < 4; r++) acc[mi][ni][r] = 0.f;

    const char* aBase = (const char*)g_A + (size_t)row0 * 64;
    const char* bBase = (const char*)g_Bt + ((size_t)layer * 16 * 256 + n0) * 64;

    auto issue = [&](int kt, int st) {
        uint32_t mb = mbar_base + st * 8;
        MBARRIER_EXPECT_TX(mb, STAGE_B);
        uint32_t d = s_base + st * STAGE_B;
        BULK_CP(d,            aBase + (size_t)kt * N_PAD * 64, A_TILE_B, mb);
        BULK_CP(d + A_TILE_B, bBase + (size_t)kt * 256 * 64,   B_TILE_B, mb);
    };

    if (tid == 0) { issue(0, 0); issue(1, 1); }

    for (int kt = 0; kt < 16; kt++) {
        int st = kt % N_STAGE;
        if (tid == 0 && kt + 2 < 16) issue(kt + 2, (kt + 2) % N_STAGE);

        MBARRIER_WAIT_PARITY(mbar_base + st * 8, (kt / N_STAGE) & 1);

        uint32_t sa = s_base + st * STAGE_B;
        uint32_t sb = sa + A_TILE_B;

#pragma unroll
        for (int ks = 0; ks < 2; ks++) {
            uint32_t ao = ks ? a_off1 : a_off0;
            uint32_t bo = ks ? b_off1 : b_off0;
            uint32_t bh[4][2];
#pragma unroll
            for (int ni = 0; ni < 4; ni++)
                LDSM_X2(bh[ni][0], bh[ni][1], sb + (uint32_t)((warp_n + ni * 8) * 64) + bo);
#pragma unroll
            for (int mi = 0; mi < 4; mi++) {
                uint32_t ah[4];
                LDSM_X4(ah[0], ah[1], ah[2], ah[3], sa + (uint32_t)((warp_m + mi * 16) * 64) + ao);
#pragma unroll
                for (int ni = 0; ni < 4; ni++) mma_f32acc(acc[mi][ni], ah, bh[ni][0], bh[ni][1]);
            }
        }
        __syncthreads();
    }

    // direct epilogue (32B-per-quad stores are sector-efficient)
#pragma unroll
    for (int mi = 0; mi < 4; mi++) {
#pragma unroll
        for (int ni = 0; ni < 4; ni++) {
            int lc = warp_n + ni * 8 + tg * 2;
            float bx = bias_s[lc], by = bias_s[lc + 1];
            int gc  = n0 + lc;
            int gr0 = row0 + warp_m + mi * 16 + g;
            int gr1 = gr0 + 8;
            float2 v0, v1;
            v0.x = acc[mi][ni][0] + bx; v0.y = acc[mi][ni][1] + by;
            v1.x = acc[mi][ni][2] + bx; v1.y = acc[mi][ni][3] + by;
            if (RELU) {
                v0.x = fmaxf(v0.x, 0.f); v0.y = fmaxf(v0.y, 0.f);
                v1.x = fmaxf(v1.x, 0.f); v1.y = fmaxf(v1.y, 0.f);
            }
            if (OUT_FP16) {
                if (gr0 < N_NODES) g_feat[(size_t)gr0 * 128 + (gc >> 1)] = pack_f2h2(v0.x, v0.y);
                if (gr1 < N_NODES) g_feat[(size_t)gr1 * 128 + (gc >> 1)] = pack_f2h2(v1.x, v1.y);
            } else {
                if (gr0 < N_NODES) *(float2*)&out_param[(size_t)gr0 * D + gc] = v0;
                if (gr1 < N_NODES) *(float2*)&out_param[(size_t)gr1 * D + gc] = v1;
            }
        }
    }
}

// ---------------- launch ----------------
extern "C" void kernel_launch(void* const* d_in, const int* in_sizes, int n_in,
                              void* d_out, int out_size)
{
    const float* x   = (const float*)d_in[0];
    const int*   ei  = (const int*)d_in[1];     // JAX randint -> int32 (x64 disabled)
    const float* W1l = (const float*)d_in[2];
    const float* b1  = (const float*)d_in[3];
    const float* W1r = (const float*)d_in[4];
    const float* W2l = (const float*)d_in[5];
    const float* b2  = (const float*)d_in[6];
    const float* W2r = (const float*)d_in[7];
    float*       out = (float*)d_out;

    int E = in_sizes[1] / 2;
    if (E > E_MAX) E = E_MAX;

    cudaFuncSetAttribute(gemm_f16_kernel<true, true>,
                         cudaFuncAttributeMaxDynamicSharedMemorySize, SM_DYN);
    cudaFuncSetAttribute(gemm_f16_kernel<false, false>,
                         cudaFuncAttributeMaxDynamicSharedMemorySize, SM_DYN);

    int nb_count = (E + 255) / 256;
    int nb_conv  = (N_NODES * 128 + 255) / 256;
    int nb_w     = 512;

    // 0: degree count + x->fp16 + W convert (fused)
    prep_kernel<<<nb_count + nb_conv + nb_w, 256>>>(ei, x, W1l, W1r, W2l, W2r,
                                                    E, nb_count, nb_conv);
    // 1: scan (re-zeros deg for next replay)
    scanall_kernel<<<1, 1024>>>(E);
    // 2: CSR scatter
    scatter_kernel<<<nb_count, 256>>>(ei, E);
    // 3: layer-1 aggregation (profiled slot)
    aggregate_kernel<<<N_NODES / 4, 128>>>();

    dim3 ggrid(N_PAD / 128, 2);   // 392 x 2
    // 4: layer-1 GEMM -> g_feat (fp16 relu h)
    gemm_f16_kernel<true, true><<<ggrid, 256, SM_DYN>>>(0, b1, nullptr);
    // 5: layer-2 aggregation
    aggregate_kernel<<<N_NODES / 4, 128>>>();
    // 6: layer-2 GEMM -> out (f32)
    gemm_f16_kernel<false, false><<<ggrid, 256, SM_DYN>>>(1, b2, out);
}